// round 2
// baseline (speedup 1.0000x reference)
#include <cuda_runtime.h>
#include <cstdint>

#define N_NODES   100000
#define N_EDGES   640000
#define IN_FEAT   128

// Scratch: per-node scores (alloc-free rule -> __device__ globals)
__device__ float g_score_src[N_NODES];
__device__ float g_score_trg[N_NODES];

// ---------------------------------------------------------------------------
// Kernel 1: per-node dual dot products.
// One warp per node. Lane i loads x[node][4i..4i+3] as float4 (coalesced 512B
// per warp), dots against W_src / W_trg (tiny, L1-resident), warp-reduces.
// ---------------------------------------------------------------------------
__global__ __launch_bounds__(256) void node_scores_kernel(
    const float* __restrict__ x,     // [N_NODES, 128]
    const float* __restrict__ W)     // [1, 256] = [W_src(128) | W_trg(128)]
{
    const int warp_in_block = threadIdx.x >> 5;
    const int lane          = threadIdx.x & 31;
    const int node          = blockIdx.x * 8 + warp_in_block;
    if (node >= N_NODES) return;

    const float4 xv = __ldg(reinterpret_cast<const float4*>(x + (size_t)node * IN_FEAT) + lane);
    const float4 ws = __ldg(reinterpret_cast<const float4*>(W)            + lane);
    const float4 wt = __ldg(reinterpret_cast<const float4*>(W + IN_FEAT)  + lane);

    float ss = xv.x * ws.x + xv.y * ws.y + xv.z * ws.z + xv.w * ws.w;
    float st = xv.x * wt.x + xv.y * wt.y + xv.z * wt.z + xv.w * wt.w;

    #pragma unroll
    for (int off = 16; off > 0; off >>= 1) {
        ss += __shfl_xor_sync(0xFFFFFFFFu, ss, off);
        st += __shfl_xor_sync(0xFFFFFFFFu, st, off);
    }
    if (lane == 0) {
        g_score_src[node] = ss;
        g_score_trg[node] = st;
    }
}

// ---------------------------------------------------------------------------
// Kernel 2: per-edge gather + sigmoid.
// Edge indices are INT32 (JAX x64-disabled downgrades the int64 request).
// Coalesced int4-wide index reads (4 edges/thread); random 4B gathers into
// the 800KB score table (L2-resident).
// ---------------------------------------------------------------------------
__global__ __launch_bounds__(256) void edge_sigmoid_kernel(
    const int*   __restrict__ edge_src,
    const int*   __restrict__ edge_trg,
    const float* __restrict__ b,
    float*       __restrict__ out)
{
    const int e4 = blockIdx.x * blockDim.x + threadIdx.x;   // group of 4 edges
    const int e  = e4 * 4;
    if (e >= N_EDGES) return;

    const float bias = __ldg(b);

    const int4 s4 = __ldg(reinterpret_cast<const int4*>(edge_src) + e4);
    const int4 t4 = __ldg(reinterpret_cast<const int4*>(edge_trg) + e4);

    float4 r;
    {
        float z = g_score_src[s4.x] + g_score_trg[t4.x] + bias;
        r.x = 1.0f / (1.0f + __expf(-z));
        z = g_score_src[s4.y] + g_score_trg[t4.y] + bias;
        r.y = 1.0f / (1.0f + __expf(-z));
        z = g_score_src[s4.z] + g_score_trg[t4.z] + bias;
        r.z = 1.0f / (1.0f + __expf(-z));
        z = g_score_src[s4.w] + g_score_trg[t4.w] + bias;
        r.w = 1.0f / (1.0f + __expf(-z));
    }
    reinterpret_cast<float4*>(out)[e4] = r;
}

// ---------------------------------------------------------------------------
extern "C" void kernel_launch(void* const* d_in, const int* in_sizes, int n_in,
                              void* d_out, int out_size)
{
    // Identify inputs defensively by element count.
    const float* x  = nullptr;
    const int*   es = nullptr;
    const int*   et = nullptr;
    const float* W  = nullptr;
    const float* b  = nullptr;

    for (int i = 0; i < n_in; ++i) {
        const int n = in_sizes[i];
        if (n == N_NODES * IN_FEAT)      x = (const float*)d_in[i];
        else if (n == N_EDGES) {
            if (!es) es = (const int*)d_in[i];
            else     et = (const int*)d_in[i];
        }
        else if (n == 2 * IN_FEAT)       W = (const float*)d_in[i];
        else if (n == 1)                 b = (const float*)d_in[i];
    }

    float* out = (float*)d_out;

    // Kernel 1: 8 nodes per 256-thread block
    const int blocks1 = (N_NODES + 7) / 8;
    node_scores_kernel<<<blocks1, 256>>>(x, W);

    // Kernel 2: 4 edges per thread, N_EDGES/4 = 160000 threads
    const int threads2 = N_EDGES / 4;                 // divides exactly
    const int blocks2  = (threads2 + 255) / 256;
    edge_sigmoid_kernel<<<blocks2, 256>>>(es, et, b, out);
}

// round 3
// speedup vs baseline: 1.0952x; 1.0952x over previous
#include <cuda_runtime.h>
#include <cstdint>

#define N_NODES   100000
#define N_EDGES   640000
#define IN_FEAT   128

// Scratch: per-node scores (alloc-free rule -> __device__ globals)
__device__ float g_score_src[N_NODES];
__device__ float g_score_trg[N_NODES];

// ---------------------------------------------------------------------------
// Kernel 1: per-node dual dot products, 2 nodes per warp (MLP=2).
// Lane i loads float4 #i of node A's row and node B's row (2 independent
// LDG.128 in flight). Four shuffle-reduction trees interleaved for ILP.
// ---------------------------------------------------------------------------
__global__ __launch_bounds__(512) void node_scores_kernel(
    const float* __restrict__ x,     // [N_NODES, 128]
    const float* __restrict__ W)     // [1, 256] = [W_src(128) | W_trg(128)]
{
    const int warp_in_block = threadIdx.x >> 5;
    const int lane          = threadIdx.x & 31;
    // each warp handles nodes (2*w) and (2*w + 1)
    const int w     = blockIdx.x * 16 + warp_in_block;
    const int nodeA = 2 * w;
    const int nodeB = 2 * w + 1;
    if (nodeA >= N_NODES) return;

    const float4 ws = __ldg(reinterpret_cast<const float4*>(W)           + lane);
    const float4 wt = __ldg(reinterpret_cast<const float4*>(W + IN_FEAT) + lane);

    const float4 xa = __ldg(reinterpret_cast<const float4*>(x + (size_t)nodeA * IN_FEAT) + lane);
    // nodeB always < N_NODES when nodeA is (N_NODES is even)
    const float4 xb = __ldg(reinterpret_cast<const float4*>(x + (size_t)nodeB * IN_FEAT) + lane);

    float ssA = xa.x * ws.x + xa.y * ws.y + xa.z * ws.z + xa.w * ws.w;
    float stA = xa.x * wt.x + xa.y * wt.y + xa.z * wt.z + xa.w * wt.w;
    float ssB = xb.x * ws.x + xb.y * ws.y + xb.z * ws.z + xb.w * ws.w;
    float stB = xb.x * wt.x + xb.y * wt.y + xb.z * wt.z + xb.w * wt.w;

    #pragma unroll
    for (int off = 16; off > 0; off >>= 1) {
        ssA += __shfl_xor_sync(0xFFFFFFFFu, ssA, off);
        stA += __shfl_xor_sync(0xFFFFFFFFu, stA, off);
        ssB += __shfl_xor_sync(0xFFFFFFFFu, ssB, off);
        stB += __shfl_xor_sync(0xFFFFFFFFu, stB, off);
    }
    if (lane == 0) {
        g_score_src[nodeA] = ssA;
        g_score_trg[nodeA] = stA;
        g_score_src[nodeB] = ssB;
        g_score_trg[nodeB] = stB;
    }
}

// ---------------------------------------------------------------------------
// Kernel 2: per-edge gather + sigmoid, 2 edges per thread.
// 320K threads (~full occupancy) to hide L1tex wavefront latency of the
// 1.28M random 4B gathers into the L2/L1-resident 800KB score tables.
// ---------------------------------------------------------------------------
__global__ __launch_bounds__(256) void edge_sigmoid_kernel(
    const int*   __restrict__ edge_src,
    const int*   __restrict__ edge_trg,
    const float* __restrict__ b,
    float*       __restrict__ out)
{
    const int e2 = blockIdx.x * blockDim.x + threadIdx.x;   // group of 2 edges
    if (e2 * 2 >= N_EDGES) return;

    const float bias = __ldg(b);

    const int2 s2 = __ldg(reinterpret_cast<const int2*>(edge_src) + e2);
    const int2 t2 = __ldg(reinterpret_cast<const int2*>(edge_trg) + e2);

    // issue all 4 gathers before consuming (compiler batches LDGs)
    const float a0 = g_score_src[s2.x];
    const float a1 = g_score_src[s2.y];
    const float c0 = g_score_trg[t2.x];
    const float c1 = g_score_trg[t2.y];

    float2 r;
    float z0 = a0 + c0 + bias;
    float z1 = a1 + c1 + bias;
    r.x = 1.0f / (1.0f + __expf(-z0));
    r.y = 1.0f / (1.0f + __expf(-z1));

    reinterpret_cast<float2*>(out)[e2] = r;
}

// ---------------------------------------------------------------------------
extern "C" void kernel_launch(void* const* d_in, const int* in_sizes, int n_in,
                              void* d_out, int out_size)
{
    // Identify inputs defensively by element count.
    const float* x  = nullptr;
    const int*   es = nullptr;
    const int*   et = nullptr;
    const float* W  = nullptr;
    const float* b  = nullptr;

    for (int i = 0; i < n_in; ++i) {
        const int n = in_sizes[i];
        if (n == N_NODES * IN_FEAT)      x = (const float*)d_in[i];
        else if (n == N_EDGES) {
            if (!es) es = (const int*)d_in[i];
            else     et = (const int*)d_in[i];
        }
        else if (n == 2 * IN_FEAT)       W = (const float*)d_in[i];
        else if (n == 1)                 b = (const float*)d_in[i];
    }

    float* out = (float*)d_out;

    // Kernel 1: 16 warps/block, 2 nodes/warp -> 32 nodes/block
    const int blocks1 = (N_NODES + 31) / 32;
    node_scores_kernel<<<blocks1, 512>>>(x, W);

    // Kernel 2: 2 edges per thread -> 320K threads
    const int threads2 = N_EDGES / 2;                 // divides exactly
    const int blocks2  = (threads2 + 255) / 256;
    edge_sigmoid_kernel<<<blocks2, 256>>>(es, et, b, out);
}